// round 13
// baseline (speedup 1.0000x reference)
#include <cuda_runtime.h>
#include <cuda_fp16.h>
#include <math.h>
#include <cstdint>

#define NB 4096
#define ND 128
#define NT 512                    // 32 (M) x 16 (N) tiles of 128x256
#define GRID_SIM 296              // 2 CTAs per SM, persistent
#define STRIDE 144                // smem bytes per 128-col fp8 row (128 + 16 pad)
#define SM_TILEA (128 * STRIDE)   // 18432 B
#define SM_TILEB (256 * STRIDE)   // 36864 B
#define BUF_BYTES (SM_TILEA + SM_TILEB)   // 55296 B
#define SM_TOTAL (2 * BUF_BYTES)          // 110592 B
// z scaled by sqrt(4*log2(e)) = 2.4022448 -> accumulator = sim * 4*log2(e),
// so exp(sim/T) = ex2(accumulator) directly.
#define NORM_SCALE 2.4022448f

// ---------------- scratch (no allocations allowed) ----------------
__device__ __align__(16) uint32_t g_zi_f8[NB * 32];  // e4m3 z_i*2.4022
__device__ __align__(16) uint32_t g_zj_f8[NB * 32];  // e4m3 z_j*2.4022
__device__ float g_rowsum[NB];
__device__ float g_colsum[NB];
__device__ float g_pos[NB];

__device__ __forceinline__ uint32_t smem_u32(const void* p) {
    uint32_t a;
    asm("{ .reg .u64 t; cvta.to.shared.u64 t, %1; cvt.u32.u64 %0, t; }" : "=r"(a) : "l"(p));
    return a;
}
__device__ __forceinline__ void cp16(uint32_t dst, const void* src) {
    asm volatile("cp.async.cg.shared.global [%0], [%1], 16;" :: "r"(dst), "l"(src));
}
__device__ __forceinline__ void ldm_x4(uint32_t& r0, uint32_t& r1, uint32_t& r2,
                                       uint32_t& r3, uint32_t addr) {
    asm volatile("ldmatrix.sync.aligned.m8n8.x4.shared.b16 {%0,%1,%2,%3}, [%4];"
                 : "=r"(r0), "=r"(r1), "=r"(r2), "=r"(r3) : "r"(addr));
}
__device__ __forceinline__ void mma_fp8_h(uint32_t& c0, uint32_t& c1,
                                          uint32_t a0, uint32_t a1, uint32_t a2, uint32_t a3,
                                          uint32_t b0, uint32_t b1) {
    asm volatile("mma.sync.aligned.m16n8k32.row.col.f16.e4m3.e4m3.f16 "
                 "{%0,%1}, {%2,%3,%4,%5}, {%6,%7}, {%0,%1};"
                 : "+r"(c0), "+r"(c1)
                 : "r"(a0), "r"(a1), "r"(a2), "r"(a3), "r"(b0), "r"(b1));
}
__device__ __forceinline__ uint32_t ex2h2(uint32_t x) {
    uint32_t r;
    asm("ex2.approx.f16x2 %0, %1;" : "=r"(r) : "r"(x));
    return r;
}
__device__ __forceinline__ uint32_t haddu(uint32_t a, uint32_t b) {
    uint32_t r;
    asm("add.rn.f16x2 %0, %1, %2;" : "=r"(r) : "r"(a), "r"(b));
    return r;
}
__device__ __forceinline__ float2 h2f2(uint32_t h) {
    __half2 v = *(__half2*)&h;
    return __half22float2(v);
}
__device__ __forceinline__ uint32_t pack_e4m3(float x, float y, float z, float w) {
    uint16_t lo, hi;
    asm("cvt.rn.satfinite.e4m3x2.f32 %0, %1, %2;" : "=h"(lo) : "f"(y), "f"(x));
    asm("cvt.rn.satfinite.e4m3x2.f32 %0, %1, %2;" : "=h"(hi) : "f"(w), "f"(z));
    return (uint32_t)lo | ((uint32_t)hi << 16);
}

// ---------------------------------------------------------------------------
// Kernel 1: single-wave persistent normalize. Warp handles rows wg, wg+2368
// with all loads front-batched (MLP=8 per thread).
// ---------------------------------------------------------------------------
__global__ void __launch_bounds__(256) norm_kernel(const float* __restrict__ emb_i,
                                                   const float* __restrict__ emb_j) {
    int l = threadIdx.x & 31;
    int wg = blockIdx.x * 8 + (threadIdx.x >> 5);      // [0, 2368)
    int r0 = wg;
    int r1 = wg + 2368;                                // may be >= NB
    bool has2 = (r1 < NB);

    const float4* EI = (const float4*)emb_i;
    const float4* EJ = (const float4*)emb_j;
    float4 a0 = EI[r0 * 32 + l];
    float4 b0 = EJ[r0 * 32 + l];
    float4 a1, b1;
    if (has2) { a1 = EI[r1 * 32 + l]; b1 = EJ[r1 * 32 + l]; }

    float s0i = a0.x*a0.x + a0.y*a0.y + a0.z*a0.z + a0.w*a0.w;
    float s0j = b0.x*b0.x + b0.y*b0.y + b0.z*b0.z + b0.w*b0.w;
    float d0  = a0.x*b0.x + a0.y*b0.y + a0.z*b0.z + a0.w*b0.w;
    float s1i = 0.f, s1j = 0.f, d1 = 0.f;
    if (has2) {
        s1i = a1.x*a1.x + a1.y*a1.y + a1.z*a1.z + a1.w*a1.w;
        s1j = b1.x*b1.x + b1.y*b1.y + b1.z*b1.z + b1.w*b1.w;
        d1  = a1.x*b1.x + a1.y*b1.y + a1.z*b1.z + a1.w*b1.w;
    }
#pragma unroll
    for (int o = 16; o > 0; o >>= 1) {
        s0i += __shfl_xor_sync(0xffffffffu, s0i, o);
        s0j += __shfl_xor_sync(0xffffffffu, s0j, o);
        d0  += __shfl_xor_sync(0xffffffffu, d0,  o);
        s1i += __shfl_xor_sync(0xffffffffu, s1i, o);
        s1j += __shfl_xor_sync(0xffffffffu, s1j, o);
        d1  += __shfl_xor_sync(0xffffffffu, d1,  o);
    }
    float i0 = 1.0f / fmaxf(sqrtf(s0i), 1e-12f);
    float j0 = 1.0f / fmaxf(sqrtf(s0j), 1e-12f);
    float si = i0 * NORM_SCALE, sj = j0 * NORM_SCALE;
    g_zi_f8[r0 * 32 + l] = pack_e4m3(a0.x*si, a0.y*si, a0.z*si, a0.w*si);
    g_zj_f8[r0 * 32 + l] = pack_e4m3(b0.x*sj, b0.y*sj, b0.z*sj, b0.w*sj);
    if (l == 0) {
        g_pos[r0] = d0 * i0 * j0;
        g_rowsum[r0] = 0.0f;
        g_colsum[r0] = 0.0f;
    }
    if (has2) {
        float i1 = 1.0f / fmaxf(sqrtf(s1i), 1e-12f);
        float j1 = 1.0f / fmaxf(sqrtf(s1j), 1e-12f);
        si = i1 * NORM_SCALE; sj = j1 * NORM_SCALE;
        g_zi_f8[r1 * 32 + l] = pack_e4m3(a1.x*si, a1.y*si, a1.z*si, a1.w*si);
        g_zj_f8[r1 * 32 + l] = pack_e4m3(b1.x*sj, b1.y*sj, b1.z*sj, b1.w*sj);
        if (l == 0) {
            g_pos[r1] = d1 * i1 * j1;
            g_rowsum[r1] = 0.0f;
            g_colsum[r1] = 0.0f;
        }
    }
}

// ---------------------------------------------------------------------------
// Kernel 2: persistent fp8 MMA, CTA tile 128(M) x 256(N), warp tile 64x64.
// 8 warps = 2(m) x 4(n). Double-buffered, single sync/iter, REDG epilogue.
// ---------------------------------------------------------------------------
__device__ __forceinline__ void prefetch_tile(int t, uint32_t dst, int tid) {
    int bx = t & 15, by = t >> 4;
    const char* srcA = (const char*)g_zi_f8 + (size_t)by * 128 * 128;
    const char* srcB = (const char*)g_zj_f8 + (size_t)bx * 256 * 128;
#pragma unroll
    for (int it = 0; it < 4; it++) {                 // A: 128 rows
        int i = it * 256 + tid;                      // [0,1024)
        uint32_t soff = (uint32_t)(i >> 3) * STRIDE + (uint32_t)(i & 7) * 16;
        cp16(dst + soff, srcA + (size_t)i * 16);
    }
#pragma unroll
    for (int it = 0; it < 8; it++) {                 // B: 256 rows
        int i = it * 256 + tid;                      // [0,2048)
        uint32_t soff = (uint32_t)(i >> 3) * STRIDE + (uint32_t)(i & 7) * 16;
        cp16(dst + SM_TILEA + soff, srcB + (size_t)i * 16);
    }
    asm volatile("cp.async.commit_group;" ::: "memory");
}

__global__ void __launch_bounds__(256, 2) sim_kernel() {
    extern __shared__ char smem[];
    uint32_t sbase = smem_u32(smem);
    int tid = threadIdx.x;
    int wid = tid >> 5;
    int l = tid & 31;
    int m_base = (wid & 1) * 64;                     // 2 m-groups
    int n_base = (wid >> 1) * 64;                    // 4 n-groups of 64
    uint32_t lrow  = (uint32_t)(((l >> 3) & 1) * 8 + (l & 7));
    uint32_t lcolb = (uint32_t)((l >> 4) * 16);

    int t = blockIdx.x;
    if (t < NT) prefetch_tile(t, sbase, tid);        // prologue: buffer 0
    int buf = 0;

    for (; t < NT; t += GRID_SIM) {
        asm volatile("cp.async.wait_group 0;" ::: "memory");
        __syncthreads();     // cur tile resident; all warps done with buf^1
        int tn = t + GRID_SIM;
        if (tn < NT)
            prefetch_tile(tn, sbase + (uint32_t)(buf ^ 1) * BUF_BYTES, tid);

        uint32_t cur = sbase + (uint32_t)buf * BUF_BYTES;
        uint32_t a_base = cur + (m_base + lrow) * STRIDE + lcolb;
        uint32_t b_base = cur + SM_TILEA + (n_base + lrow) * STRIDE + lcolb;

        uint32_t c[4][8][2];                         // packed half2 accums (64 regs)
#pragma unroll
        for (int mf = 0; mf < 4; mf++)
#pragma unroll
            for (int nf = 0; nf < 8; nf++) { c[mf][nf][0] = 0u; c[mf][nf][1] = 0u; }

#pragma unroll
        for (int ks = 0; ks < 4; ks++) {             // K=128 fp8, 32 per MMA
            uint32_t koff = (uint32_t)ks * 32;
            uint32_t a0[4], a1[4], a2[4], a3[4];
#pragma unroll
            for (int mf = 0; mf < 4; mf++)
                ldm_x4(a0[mf], a1[mf], a2[mf], a3[mf],
                       a_base + (uint32_t)mf * 16 * STRIDE + koff);
            uint32_t bl0[4], bl1[4], bl2[4], bl3[4];
#pragma unroll
            for (int nh = 0; nh < 4; nh++)
                ldm_x4(bl0[nh], bl1[nh], bl2[nh], bl3[nh],
                       b_base + (uint32_t)nh * 16 * STRIDE + koff);
#pragma unroll
            for (int mf = 0; mf < 4; mf++) {
#pragma unroll
                for (int nh = 0; nh < 4; nh++) {
                    mma_fp8_h(c[mf][nh * 2][0], c[mf][nh * 2][1],
                              a0[mf], a1[mf], a2[mf], a3[mf], bl0[nh], bl2[nh]);
                    mma_fp8_h(c[mf][nh * 2 + 1][0], c[mf][nh * 2 + 1][1],
                              a0[mf], a1[mf], a2[mf], a3[mf], bl1[nh], bl3[nh]);
                }
            }
        }

        // --- epilogue: ex2.f16x2 + packed-half2 sums -> direct global REDG ---
        // c0 -> rows r @ (cc,cc+1); c1 -> rows r+8; r=l/4, cc=2(l%4)
        int rowBase = (t >> 4) * 128;
        int colBase = (t & 15) * 256;
        uint32_t hr0[4], hr1[4], cacc[8];
#pragma unroll
        for (int i = 0; i < 4; i++) { hr0[i] = 0u; hr1[i] = 0u; }
#pragma unroll
        for (int i = 0; i < 8; i++) cacc[i] = 0u;
#pragma unroll
        for (int mf = 0; mf < 4; mf++) {
#pragma unroll
            for (int nf = 0; nf < 8; nf++) {
                uint32_t e0 = ex2h2(c[mf][nf][0]);
                uint32_t e1 = ex2h2(c[mf][nf][1]);
                hr0[mf] = haddu(hr0[mf], e0);
                hr1[mf] = haddu(hr1[mf], e1);
                cacc[nf] = haddu(cacc[nf], haddu(e0, e1));
            }
        }
        // rows: packed shuffle over col-pair lanes (l&3), then REDG pair
#pragma unroll
        for (int mf = 0; mf < 4; mf++) {
            uint32_t a = hr0[mf], b = hr1[mf];
#pragma unroll
            for (int o = 1; o <= 2; o <<= 1) {
                a = haddu(a, __shfl_xor_sync(0xffffffffu, a, o));
                b = haddu(b, __shfl_xor_sync(0xffffffffu, b, o));
            }
            if ((l & 3) == 0) {
                float2 fa = h2f2(a), fb = h2f2(b);
                int r = rowBase + m_base + mf * 16 + (l >> 2);
                atomicAdd(&g_rowsum[r], fa.x + fa.y);
                atomicAdd(&g_rowsum[r + 8], fb.x + fb.y);
            }
        }
        // cols: packed shuffle over row lanes (l>>2), then REDG per component
#pragma unroll
        for (int nf = 0; nf < 8; nf++) {
            uint32_t a = cacc[nf];
#pragma unroll
            for (int o = 4; o <= 16; o <<= 1)
                a = haddu(a, __shfl_xor_sync(0xffffffffu, a, o));
            if (l < 4) {
                float2 fa = h2f2(a);
                int cc = colBase + n_base + nf * 8 + 2 * l;
                atomicAdd(&g_colsum[cc], fa.x);
                atomicAdd(&g_colsum[cc + 1], fa.y);
            }
        }
        buf ^= 1;
    }
}

// ---------------------------------------------------------------------------
// Kernel 3: loss = ( sum log(rowsum)+log(colsum) - (2/T) sum pos ) / 2B
// ---------------------------------------------------------------------------
__global__ void __launch_bounds__(512) final_kernel(float* __restrict__ out) {
    int t = threadIdx.x;
    double acc = 0.0;
    for (int i = t; i < NB; i += 512) {
        acc += (double)__logf(g_rowsum[i]) + (double)__logf(g_colsum[i])
             - 8.0 * (double)g_pos[i];                        // 2/T = 8
    }
    __shared__ double sd[512];
    sd[t] = acc;
    __syncthreads();
#pragma unroll
    for (int o = 256; o > 0; o >>= 1) {
        if (t < o) sd[t] += sd[t + o];
        __syncthreads();
    }
    if (t == 0) out[0] = (float)(sd[0] / (2.0 * NB));
}

extern "C" void kernel_launch(void* const* d_in, const int* in_sizes, int n_in,
                              void* d_out, int out_size) {
    const float* emb_i = (const float*)d_in[0];
    const float* emb_j = (const float*)d_in[1];
    float* out = (float*)d_out;

    cudaFuncSetAttribute(sim_kernel, cudaFuncAttributeMaxDynamicSharedMemorySize, SM_TOTAL);

    norm_kernel<<<GRID_SIM, 256>>>(emb_i, emb_j);
    sim_kernel<<<GRID_SIM, 256, SM_TOTAL>>>();
    final_kernel<<<1, 512>>>(out);
}